// round 5
// baseline (speedup 1.0000x reference)
#include <cuda_runtime.h>
#include <cuda_bf16.h>
#include <math.h>

#define N_NODES 50000
#define N_EDGES 800000
#define IN_SIZE 128
#define HID 32
#define H1 8
#define OUTC 40
#define F1 (H1 * HID)   // 256
#define NEG_SLOPE 0.2f

#define NB_SCAN ((N_NODES + 1023) / 1024)   // 49

typedef unsigned long long ull;

// ---------------- scratch ----------------
__device__ int   g_deg[N_NODES];
__device__ int   g_rowptr[N_NODES + 1];
__device__ int   g_wcur[N_NODES];
__device__ int   g_bsum[64];
__device__ int   g_col[N_EDGES];          // src per CSR slot
__device__ int   g_dstslot[N_EDGES];      // dst per CSR slot
__device__ float g_ex1[N_EDGES * H1];     // softmax numerator per (slot, head)
__device__ float g_ex2[N_EDGES];          // layer-2 numerator per slot
__device__ float g_z1[N_NODES * F1];
__device__ float g_el1[N_NODES * H1];
__device__ float g_er1[N_NODES * H1];
__device__ float g_h1[N_NODES * F1];
__device__ float g_z2[N_NODES * OUTC];
__device__ float g_el2[N_NODES];
__device__ float g_er2[N_NODES];

// ---------------- f32x2 helpers (sm_100+) ----------------
__device__ __forceinline__ ull ffma2(ull a, ull b, ull c) {
    ull d;
    asm("fma.rn.f32x2 %0, %1, %2, %3;" : "=l"(d) : "l"(a), "l"(b), "l"(c));
    return d;
}
__device__ __forceinline__ ull pack2(float lo, float hi) {
    ull d;
    asm("mov.b64 %0, {%1, %2};" : "=l"(d) : "f"(lo), "f"(hi));
    return d;
}
__device__ __forceinline__ void unpack2(ull v, float& lo, float& hi) {
    asm("mov.b64 {%0, %1}, %2;" : "=f"(lo), "=f"(hi) : "l"(v));
}

__device__ __forceinline__ float lrelu(float a) { return fmaxf(a, NEG_SLOPE * a); }

// ---------------- CSR build ----------------
__global__ void zero_deg_kernel() {
    int i = blockIdx.x * 1024 + threadIdx.x;
    if (i < N_NODES) g_deg[i] = 0;
}

__global__ void count_kernel(const int* __restrict__ dst) {
    int e = blockIdx.x * 256 + threadIdx.x;
    if (e < N_EDGES) atomicAdd(&g_deg[dst[e]], 1);
}

__global__ void scan1_kernel() {
    int i = blockIdx.x * 1024 + threadIdx.x;
    int v = (i < N_NODES) ? g_deg[i] : 0;
    int lane = threadIdx.x & 31, w = threadIdx.x >> 5;
    int x = v;
    #pragma unroll
    for (int o = 1; o < 32; o <<= 1) {
        int y = __shfl_up_sync(0xffffffffu, x, o);
        if (lane >= o) x += y;
    }
    __shared__ int ws[32];
    if (lane == 31) ws[w] = x;
    __syncthreads();
    if (w == 0) {
        int s = ws[lane];
        #pragma unroll
        for (int o = 1; o < 32; o <<= 1) {
            int y = __shfl_up_sync(0xffffffffu, s, o);
            if (lane >= o) s += y;
        }
        ws[lane] = s;
    }
    __syncthreads();
    int pre = (w > 0) ? ws[w - 1] : 0;
    int incl = pre + x;
    if (i < N_NODES) g_rowptr[i] = incl - v;   // block-local exclusive
    if (threadIdx.x == 1023) g_bsum[blockIdx.x] = incl;
}

__global__ void scan2_kernel() {
    if (threadIdx.x == 0) {
        int run = 0;
        for (int b = 0; b < NB_SCAN; b++) { int t = g_bsum[b]; g_bsum[b] = run; run += t; }
        g_rowptr[N_NODES] = run;
    }
}

__global__ void scan3_kernel() {
    int i = blockIdx.x * 1024 + threadIdx.x;
    if (i < N_NODES) {
        int v = g_rowptr[i] + g_bsum[blockIdx.x];
        g_rowptr[i] = v;
        g_wcur[i] = v;
    }
}

__global__ void scatter_kernel(const int* __restrict__ src, const int* __restrict__ dst) {
    int e = blockIdx.x * 256 + threadIdx.x;
    if (e < N_EDGES) {
        int d = dst[e];
        int p = atomicAdd(&g_wcur[d], 1);
        g_col[p] = src[e];
        g_dstslot[p] = d;
    }
}

// ---------------- GEMM1 + fused el1/er1 ----------------
// z1[N,256] = feat[N,128] @ W1[128,256]; el1/er1 = head-wise dots with al1/ar1.
// block: 64 rows x 256 cols, full K in smem, 512 threads, 4x8 per thread,
// f32x2 packed accumulators (4 col-pairs x 4 rows). 16 warps/SM for latency hiding.
__global__ void gemm1_kernel(const float* __restrict__ feat, const float* __restrict__ W1,
                             const float* __restrict__ al1, const float* __restrict__ ar1) {
    extern __shared__ float sh[];
    float* shW  = sh;                    // [128][256]
    float* shF  = sh + 128 * 256;        // [128][64] k-major
    float* shAl = sh + 128 * 256 + 128 * 64;  // [256]
    float* shAr = shAl + 256;                 // [256]
    int tid = threadIdx.x;
    int row0 = blockIdx.x * 64;

    const float4* W4 = (const float4*)W1;
    float4* shW4 = (float4*)shW;
    #pragma unroll 4
    for (int i = tid; i < 128 * 256 / 4; i += 512) shW4[i] = W4[i];
    if (tid < 256) { shAl[tid] = al1[tid]; shAr[tid] = ar1[tid]; }
    // feat: load float4 along k, scatter to k-major. consecutive tid -> consecutive r (conflict-free STS)
    for (int i = tid; i < 2048; i += 512) {
        int r = i & 63, kc = i >> 6;
        int gr = row0 + r;
        float4 v = make_float4(0.f, 0.f, 0.f, 0.f);
        if (gr < N_NODES) v = *(const float4*)&feat[gr * 128 + kc * 4];
        shF[(kc * 4 + 0) * 64 + r] = v.x;
        shF[(kc * 4 + 1) * 64 + r] = v.y;
        shF[(kc * 4 + 2) * 64 + r] = v.z;
        shF[(kc * 4 + 3) * 64 + r] = v.w;
    }
    __syncthreads();

    int tx = tid & 31, ty = tid >> 5;     // tx: lane (col group of 8), ty: warp (row group of 4)
    int c0 = tx * 8, r0 = ty * 4;
    ull acc[4][4];
    #pragma unroll
    for (int i = 0; i < 4; i++)
        #pragma unroll
        for (int j = 0; j < 4; j++) acc[i][j] = 0ull;

    #pragma unroll 4
    for (int k = 0; k < 128; k++) {
        float4 fa = *(const float4*)&shF[k * 64 + r0];
        longlong2 wa = *(const longlong2*)&shW[k * 256 + c0];
        longlong2 wb = *(const longlong2*)&shW[k * 256 + c0 + 4];
        ull w[4] = {(ull)wa.x, (ull)wa.y, (ull)wb.x, (ull)wb.y};
        ull f[4];
        f[0] = pack2(fa.x, fa.x); f[1] = pack2(fa.y, fa.y);
        f[2] = pack2(fa.z, fa.z); f[3] = pack2(fa.w, fa.w);
        #pragma unroll
        for (int i = 0; i < 4; i++)
            #pragma unroll
            for (int j = 0; j < 4; j++)
                acc[i][j] = ffma2(f[i], w[j], acc[i][j]);
    }

    // epilogue: store z1 + fused el/er (head h = tx>>2; this thread owns cols off..off+7 of head)
    int h = tx >> 2;
    int off = (tx & 3) * 8;
    #pragma unroll
    for (int i = 0; i < 4; i++) {
        float c[8];
        #pragma unroll
        for (int j = 0; j < 4; j++) unpack2(acc[i][j], c[2 * j], c[2 * j + 1]);
        int gr = row0 + r0 + i;
        if (gr < N_NODES) {
            *(float4*)&g_z1[gr * 256 + c0]     = make_float4(c[0], c[1], c[2], c[3]);
            *(float4*)&g_z1[gr * 256 + c0 + 4] = make_float4(c[4], c[5], c[6], c[7]);
        }
        float el = 0.f, er = 0.f;
        #pragma unroll
        for (int j = 0; j < 8; j++) {
            el += c[j] * shAl[h * 32 + off + j];
            er += c[j] * shAr[h * 32 + off + j];
        }
        el += __shfl_xor_sync(0xffffffffu, el, 1);
        el += __shfl_xor_sync(0xffffffffu, el, 2);
        er += __shfl_xor_sync(0xffffffffu, er, 1);
        er += __shfl_xor_sync(0xffffffffu, er, 2);
        if ((tx & 3) == 0 && gr < N_NODES) {
            g_el1[gr * H1 + h] = el;
            g_er1[gr * H1 + h] = er;
        }
    }
}

// ---------------- edge weights layer 1: ex1[p,h] = exp(lrelu(el1[src]+er1[dst])) ----------------
__global__ void exk1_kernel() {
    int t = blockIdx.x * 256 + threadIdx.x;
    if (t >= N_EDGES * H1) return;
    int p = t >> 3, h = t & 7;
    int s = g_col[p], d = g_dstslot[p];
    float e = g_el1[s * H1 + h] + g_er1[d * H1 + h];
    g_ex1[t] = __expf(lrelu(e));
}

// ---------------- layer-1 aggregation + bias + ELU -> h1 ----------------
// one block per dst node; warp h handles head h, lane d handles dim d.
__global__ void agg1_kernel(const float* __restrict__ b1) {
    int n = blockIdx.x;
    int h = threadIdx.x >> 5, d = threadIdx.x & 31;
    int rs = g_rowptr[n], re = g_rowptr[n + 1];
    float acc = 0.f, sumex = 0.f;
    int i = rs;
    for (; i + 4 <= re; i += 4) {
        int s0 = g_col[i], s1 = g_col[i + 1], s2 = g_col[i + 2], s3 = g_col[i + 3];
        float x0 = g_ex1[(i + 0) * H1 + h];
        float x1 = g_ex1[(i + 1) * H1 + h];
        float x2 = g_ex1[(i + 2) * H1 + h];
        float x3 = g_ex1[(i + 3) * H1 + h];
        float z0 = g_z1[s0 * 256 + h * 32 + d];
        float z1v = g_z1[s1 * 256 + h * 32 + d];
        float z2v = g_z1[s2 * 256 + h * 32 + d];
        float z3v = g_z1[s3 * 256 + h * 32 + d];
        sumex += (x0 + x1) + (x2 + x3);
        acc += x0 * z0;
        acc += x1 * z1v;
        acc += x2 * z2v;
        acc += x3 * z3v;
    }
    for (; i < re; i++) {
        int s = g_col[i];
        float x = g_ex1[i * H1 + h];
        sumex += x;
        acc += x * g_z1[s * 256 + h * 32 + d];
    }
    float v = (sumex > 0.f) ? (acc / sumex) : 0.f;
    v += b1[threadIdx.x];
    g_h1[n * 256 + threadIdx.x] = (v > 0.f) ? v : (expm1f(v));
}

// ---------------- GEMM2: z2[N,40] = h1[N,256] @ W2[256,40] ----------------
__global__ void gemm2_kernel(const float* __restrict__ W2) {
    extern __shared__ float sh[];
    float* shH = sh;                  // [256][64] k-major
    float* shW = sh + 256 * 64;       // [256][40]
    int tid = threadIdx.x;
    int row0 = blockIdx.x * 64;

    for (int i = tid; i < 64 * 256; i += 320) {
        int r = i & 63, k = i >> 6;
        int gr = row0 + r;
        shH[k * 64 + r] = (gr < N_NODES) ? g_h1[gr * 256 + k] : 0.f;
    }
    for (int i = tid; i < 256 * 40; i += 320) shW[i] = W2[i];
    __syncthreads();

    int tx = tid % 40, ty = tid / 40;   // ty: 0..7 -> rows ty*8..ty*8+7
    int r0 = ty * 8;
    float acc[8];
    #pragma unroll
    for (int i = 0; i < 8; i++) acc[i] = 0.f;

    #pragma unroll 4
    for (int k = 0; k < 256; k++) {
        float w = shW[k * 40 + tx];
        float4 ha = *(const float4*)&shH[k * 64 + r0];
        float4 hb = *(const float4*)&shH[k * 64 + r0 + 4];
        acc[0] += ha.x * w; acc[1] += ha.y * w; acc[2] += ha.z * w; acc[3] += ha.w * w;
        acc[4] += hb.x * w; acc[5] += hb.y * w; acc[6] += hb.z * w; acc[7] += hb.w * w;
    }

    #pragma unroll
    for (int i = 0; i < 8; i++) {
        int gr = row0 + r0 + i;
        if (gr < N_NODES) g_z2[gr * 40 + tx] = acc[i];
    }
}

// ---------------- el2/er2 ----------------
__global__ void elr2_kernel(const float* __restrict__ al2, const float* __restrict__ ar2) {
    int n = blockIdx.x * 256 + threadIdx.x;
    if (n >= N_NODES) return;
    const float4* z4 = (const float4*)&g_z2[n * 40];
    float el = 0.f, er = 0.f;
    #pragma unroll
    for (int i = 0; i < 10; i++) {
        float4 z = z4[i];
        const float4 a = ((const float4*)al2)[i];
        const float4 r = ((const float4*)ar2)[i];
        el += z.x * a.x + z.y * a.y + z.z * a.z + z.w * a.w;
        er += z.x * r.x + z.y * r.y + z.z * r.z + z.w * r.w;
    }
    g_el2[n] = el;
    g_er2[n] = er;
}

// ---------------- edge weights layer 2 ----------------
__global__ void exk2_kernel() {
    int p = blockIdx.x * 256 + threadIdx.x;
    if (p >= N_EDGES) return;
    int s = g_col[p], d = g_dstslot[p];
    float e = g_el2[s] + g_er2[d];
    g_ex2[p] = __expf(lrelu(e));
}

// ---------------- layer-2 aggregation -> out ----------------
// 8 nodes per 320-thread block; 40 threads per node, fully independent threads.
#define AGG2_NPB 8
__global__ void agg2_kernel(const float* __restrict__ b2, float* __restrict__ out) {
    int local = threadIdx.x / 40;           // node slot within block (0..7)
    int j = threadIdx.x - local * 40;       // output column
    int n = blockIdx.x * AGG2_NPB + local;
    if (n >= N_NODES) return;
    int rs = g_rowptr[n], re = g_rowptr[n + 1];
    float acc = 0.f, sumex = 0.f;
    int i = rs;
    for (; i + 4 <= re; i += 4) {
        int s0 = g_col[i], s1 = g_col[i + 1], s2 = g_col[i + 2], s3 = g_col[i + 3];
        float x0 = g_ex2[i + 0];
        float x1 = g_ex2[i + 1];
        float x2 = g_ex2[i + 2];
        float x3 = g_ex2[i + 3];
        float z0 = g_z2[s0 * 40 + j];
        float z1v = g_z2[s1 * 40 + j];
        float z2v = g_z2[s2 * 40 + j];
        float z3v = g_z2[s3 * 40 + j];
        sumex += (x0 + x1) + (x2 + x3);
        acc += x0 * z0;
        acc += x1 * z1v;
        acc += x2 * z2v;
        acc += x3 * z3v;
    }
    for (; i < re; i++) {
        int s = g_col[i];
        float x = g_ex2[i];
        sumex += x;
        acc += x * g_z2[s * 40 + j];
    }
    float v = (sumex > 0.f) ? (acc / sumex) : 0.f;
    out[n * 40 + j] = v + b2[j];
}

// ---------------- launch ----------------
extern "C" void kernel_launch(void* const* d_in, const int* in_sizes, int n_in,
                              void* d_out, int out_size) {
    const float* feat = (const float*)d_in[0];
    const int*   src  = (const int*)d_in[1];
    const int*   dst  = (const int*)d_in[2];
    const float* W1   = (const float*)d_in[3];
    const float* al1  = (const float*)d_in[4];
    const float* ar1  = (const float*)d_in[5];
    const float* b1   = (const float*)d_in[6];
    const float* W2   = (const float*)d_in[7];
    const float* al2  = (const float*)d_in[8];
    const float* ar2  = (const float*)d_in[9];
    const float* b2   = (const float*)d_in[10];
    float* out = (float*)d_out;
    (void)in_sizes; (void)n_in; (void)out_size;

    zero_deg_kernel<<<NB_SCAN, 1024>>>();
    count_kernel<<<(N_EDGES + 255) / 256, 256>>>(dst);
    scan1_kernel<<<NB_SCAN, 1024>>>();
    scan2_kernel<<<1, 32>>>();
    scan3_kernel<<<NB_SCAN, 1024>>>();
    scatter_kernel<<<(N_EDGES + 255) / 256, 256>>>(src, dst);

    const int smem1 = (128 * 256 + 128 * 64 + 512) * sizeof(float);   // 165888
    cudaFuncSetAttribute(gemm1_kernel, cudaFuncAttributeMaxDynamicSharedMemorySize, smem1);
    gemm1_kernel<<<(N_NODES + 63) / 64, 512, smem1>>>(feat, W1, al1, ar1);

    exk1_kernel<<<(N_EDGES * H1 + 255) / 256, 256>>>();
    agg1_kernel<<<N_NODES, 256>>>(b1);

    const int smem2 = (256 * 64 + 256 * 40) * sizeof(float);    // 106496
    cudaFuncSetAttribute(gemm2_kernel, cudaFuncAttributeMaxDynamicSharedMemorySize, smem2);
    gemm2_kernel<<<(N_NODES + 63) / 64, 320, smem2>>>(W2);

    elr2_kernel<<<(N_NODES + 255) / 256, 256>>>(al2, ar2);
    exk2_kernel<<<(N_EDGES + 255) / 256, 256>>>();
    agg2_kernel<<<(N_NODES + AGG2_NPB - 1) / AGG2_NPB, AGG2_NPB * 40>>>(b2, out);
}

// round 6
// speedup vs baseline: 1.1058x; 1.1058x over previous
#include <cuda_runtime.h>
#include <cuda_bf16.h>
#include <math.h>

#define N_NODES 50000
#define N_EDGES 800000
#define IN_SIZE 128
#define HID 32
#define H1 8
#define OUTC 40
#define F1 (H1 * HID)   // 256
#define NEG_SLOPE 0.2f

#define NB_SCAN ((N_NODES + 1023) / 1024)   // 49

typedef unsigned long long ull;

// ---------------- scratch ----------------
__device__ int   g_deg[N_NODES];
__device__ int   g_rowptr[N_NODES + 1];
__device__ int   g_wcur[N_NODES];
__device__ int   g_bsum[64];
__device__ int   g_col[N_EDGES];          // src per CSR slot
__device__ int   g_dstslot[N_EDGES];      // dst per CSR slot
__device__ float g_ex1[N_EDGES * H1];     // softmax numerator per (slot, head)
__device__ float g_ex2[N_EDGES];          // layer-2 numerator per slot
__device__ float g_z1[N_NODES * F1];
__device__ float g_el1[N_NODES * H1];
__device__ float g_er1[N_NODES * H1];
__device__ float g_h1[N_NODES * F1];
__device__ float g_z2[N_NODES * OUTC];
__device__ float g_el2[N_NODES];
__device__ float g_er2[N_NODES];

// ---------------- f32x2 helpers (sm_100+) ----------------
__device__ __forceinline__ ull ffma2(ull a, ull b, ull c) {
    ull d;
    asm("fma.rn.f32x2 %0, %1, %2, %3;" : "=l"(d) : "l"(a), "l"(b), "l"(c));
    return d;
}
__device__ __forceinline__ ull pack2(float lo, float hi) {
    ull d;
    asm("mov.b64 %0, {%1, %2};" : "=l"(d) : "f"(lo), "f"(hi));
    return d;
}
__device__ __forceinline__ void unpack2(ull v, float& lo, float& hi) {
    asm("mov.b64 {%0, %1}, %2;" : "=f"(lo), "=f"(hi) : "l"(v));
}

__device__ __forceinline__ float lrelu(float a) { return fmaxf(a, NEG_SLOPE * a); }

// ---------------- CSR build ----------------
__global__ void zero_deg_kernel() {
    int i = blockIdx.x * 1024 + threadIdx.x;
    if (i < N_NODES) g_deg[i] = 0;
}

__global__ void count_kernel(const int* __restrict__ dst) {
    int e = blockIdx.x * 256 + threadIdx.x;
    if (e < N_EDGES) atomicAdd(&g_deg[dst[e]], 1);
}

__global__ void scan1_kernel() {
    int i = blockIdx.x * 1024 + threadIdx.x;
    int v = (i < N_NODES) ? g_deg[i] : 0;
    int lane = threadIdx.x & 31, w = threadIdx.x >> 5;
    int x = v;
    #pragma unroll
    for (int o = 1; o < 32; o <<= 1) {
        int y = __shfl_up_sync(0xffffffffu, x, o);
        if (lane >= o) x += y;
    }
    __shared__ int ws[32];
    if (lane == 31) ws[w] = x;
    __syncthreads();
    if (w == 0) {
        int s = ws[lane];
        #pragma unroll
        for (int o = 1; o < 32; o <<= 1) {
            int y = __shfl_up_sync(0xffffffffu, s, o);
            if (lane >= o) s += y;
        }
        ws[lane] = s;
    }
    __syncthreads();
    int pre = (w > 0) ? ws[w - 1] : 0;
    int incl = pre + x;
    if (i < N_NODES) g_rowptr[i] = incl - v;   // block-local exclusive
    if (threadIdx.x == 1023) g_bsum[blockIdx.x] = incl;
}

// parallel warp scan over NB_SCAN (<=64) block sums
__global__ void scan2_kernel() {
    int lane = threadIdx.x;
    int v0 = (lane < NB_SCAN) ? g_bsum[lane] : 0;
    int v1 = (lane + 32 < NB_SCAN) ? g_bsum[lane + 32] : 0;
    int s0 = v0, s1 = v1;
    #pragma unroll
    for (int o = 1; o < 32; o <<= 1) {
        int y0 = __shfl_up_sync(0xffffffffu, s0, o);
        int y1 = __shfl_up_sync(0xffffffffu, s1, o);
        if (lane >= o) { s0 += y0; s1 += y1; }
    }
    int tot0 = __shfl_sync(0xffffffffu, s0, 31);
    int tot1 = __shfl_sync(0xffffffffu, s1, 31);
    if (lane < NB_SCAN) g_bsum[lane] = s0 - v0;
    if (lane + 32 < NB_SCAN) g_bsum[lane + 32] = tot0 + s1 - v1;
    if (lane == 0) g_rowptr[N_NODES] = tot0 + tot1;
}

__global__ void scan3_kernel() {
    int i = blockIdx.x * 1024 + threadIdx.x;
    if (i < N_NODES) {
        int v = g_rowptr[i] + g_bsum[blockIdx.x];
        g_rowptr[i] = v;
        g_wcur[i] = v;
    }
}

__global__ void scatter_kernel(const int* __restrict__ src, const int* __restrict__ dst) {
    int e = blockIdx.x * 256 + threadIdx.x;
    if (e < N_EDGES) {
        int d = dst[e];
        int p = atomicAdd(&g_wcur[d], 1);
        g_col[p] = src[e];
        g_dstslot[p] = d;
    }
}

// ---------------- GEMM1 + fused el1/er1 ----------------
// z1[N,256] = feat[N,128] @ W1[128,256]; el1/er1 = head-wise dots with al1/ar1.
// block: 64 rows x 256 cols, full K in smem, 512 threads.
// thread tile 8 rows x 4 cols (2 f32x2 col-pairs): colgroup=tid&63, rowgroup=tid>>6.
// shW per warp = 512B coalesced, shF broadcast -> FMA-bound.
__global__ void gemm1_kernel(const float* __restrict__ feat, const float* __restrict__ W1,
                             const float* __restrict__ al1, const float* __restrict__ ar1) {
    extern __shared__ float sh[];
    float* shW  = sh;                    // [128][256]
    float* shF  = sh + 128 * 256;        // [128][64] k-major
    float* shAl = sh + 128 * 256 + 128 * 64;  // [256]
    float* shAr = shAl + 256;                 // [256]
    int tid = threadIdx.x;
    int row0 = blockIdx.x * 64;

    const float4* W4 = (const float4*)W1;
    float4* shW4 = (float4*)shW;
    #pragma unroll 4
    for (int i = tid; i < 128 * 256 / 4; i += 512) shW4[i] = W4[i];
    if (tid < 256) { shAl[tid] = al1[tid]; shAr[tid] = ar1[tid]; }
    // feat: load float4 along k, scatter to k-major
    for (int i = tid; i < 2048; i += 512) {
        int r = i & 63, kc = i >> 6;
        int gr = row0 + r;
        float4 v = make_float4(0.f, 0.f, 0.f, 0.f);
        if (gr < N_NODES) v = *(const float4*)&feat[gr * 128 + kc * 4];
        shF[(kc * 4 + 0) * 64 + r] = v.x;
        shF[(kc * 4 + 1) * 64 + r] = v.y;
        shF[(kc * 4 + 2) * 64 + r] = v.z;
        shF[(kc * 4 + 3) * 64 + r] = v.w;
    }
    __syncthreads();

    int cg = tid & 63, rg = tid >> 6;
    int c0 = cg * 4, r0 = rg * 8;
    ull acc[8][2];
    #pragma unroll
    for (int i = 0; i < 8; i++) { acc[i][0] = 0ull; acc[i][1] = 0ull; }

    #pragma unroll 4
    for (int k = 0; k < 128; k++) {
        float4 fa = *(const float4*)&shF[k * 64 + r0];
        float4 fb = *(const float4*)&shF[k * 64 + r0 + 4];
        longlong2 wa = *(const longlong2*)&shW[k * 256 + c0];
        ull w0 = (ull)wa.x, w1 = (ull)wa.y;
        ull f[8];
        f[0] = pack2(fa.x, fa.x); f[1] = pack2(fa.y, fa.y);
        f[2] = pack2(fa.z, fa.z); f[3] = pack2(fa.w, fa.w);
        f[4] = pack2(fb.x, fb.x); f[5] = pack2(fb.y, fb.y);
        f[6] = pack2(fb.z, fb.z); f[7] = pack2(fb.w, fb.w);
        #pragma unroll
        for (int i = 0; i < 8; i++) {
            acc[i][0] = ffma2(f[i], w0, acc[i][0]);
            acc[i][1] = ffma2(f[i], w1, acc[i][1]);
        }
    }

    // epilogue: store z1 + fused el/er.
    // head h = c0/32 = cg>>3; 8 lanes (cg&7) per head, each owns 4 cols.
    int h = cg >> 3;
    int off = (cg & 7) * 4;
    #pragma unroll
    for (int i = 0; i < 8; i++) {
        float c[4];
        unpack2(acc[i][0], c[0], c[1]);
        unpack2(acc[i][1], c[2], c[3]);
        int gr = row0 + r0 + i;
        if (gr < N_NODES) {
            *(float4*)&g_z1[gr * 256 + c0] = make_float4(c[0], c[1], c[2], c[3]);
        }
        float el = 0.f, er = 0.f;
        #pragma unroll
        for (int j = 0; j < 4; j++) {
            el += c[j] * shAl[h * 32 + off + j];
            er += c[j] * shAr[h * 32 + off + j];
        }
        el += __shfl_xor_sync(0xffffffffu, el, 1);
        el += __shfl_xor_sync(0xffffffffu, el, 2);
        el += __shfl_xor_sync(0xffffffffu, el, 4);
        er += __shfl_xor_sync(0xffffffffu, er, 1);
        er += __shfl_xor_sync(0xffffffffu, er, 2);
        er += __shfl_xor_sync(0xffffffffu, er, 4);
        if ((cg & 7) == 0 && gr < N_NODES) {
            g_el1[gr * H1 + h] = el;
            g_er1[gr * H1 + h] = er;
        }
    }
}

// ---------------- edge weights layer 1: ex1[p,h] = exp(lrelu(el1[src]+er1[dst])) ----------------
__global__ void exk1_kernel() {
    int t = blockIdx.x * 256 + threadIdx.x;
    if (t >= N_EDGES * H1) return;
    int p = t >> 3, h = t & 7;
    int s = g_col[p], d = g_dstslot[p];
    float e = g_el1[s * H1 + h] + g_er1[d * H1 + h];
    g_ex1[t] = __expf(lrelu(e));
}

// ---------------- layer-1 aggregation + bias + ELU -> h1 ----------------
// one block per dst node; warp h handles head h, lane d handles dim d.
__global__ void agg1_kernel(const float* __restrict__ b1) {
    int n = blockIdx.x;
    int h = threadIdx.x >> 5, d = threadIdx.x & 31;
    int rs = g_rowptr[n], re = g_rowptr[n + 1];
    float acc = 0.f, sumex = 0.f;
    int i = rs;
    for (; i + 4 <= re; i += 4) {
        int s0 = g_col[i], s1 = g_col[i + 1], s2 = g_col[i + 2], s3 = g_col[i + 3];
        float x0 = g_ex1[(i + 0) * H1 + h];
        float x1 = g_ex1[(i + 1) * H1 + h];
        float x2 = g_ex1[(i + 2) * H1 + h];
        float x3 = g_ex1[(i + 3) * H1 + h];
        float z0 = g_z1[s0 * 256 + h * 32 + d];
        float z1v = g_z1[s1 * 256 + h * 32 + d];
        float z2v = g_z1[s2 * 256 + h * 32 + d];
        float z3v = g_z1[s3 * 256 + h * 32 + d];
        sumex += (x0 + x1) + (x2 + x3);
        acc += x0 * z0;
        acc += x1 * z1v;
        acc += x2 * z2v;
        acc += x3 * z3v;
    }
    for (; i < re; i++) {
        int s = g_col[i];
        float x = g_ex1[i * H1 + h];
        sumex += x;
        acc += x * g_z1[s * 256 + h * 32 + d];
    }
    float v = (sumex > 0.f) ? (acc / sumex) : 0.f;
    v += b1[threadIdx.x];
    g_h1[n * 256 + threadIdx.x] = (v > 0.f) ? v : (expm1f(v));
}

// ---------------- GEMM2: z2[N,40] = h1[N,256] @ W2[256,40] ----------------
// f32x2 row-pair packed accumulators: thread = (col tx, rowgroup ty of 8 rows).
__global__ void gemm2_kernel(const float* __restrict__ W2) {
    extern __shared__ float sh[];
    float* shH = sh;                  // [256][64] k-major
    float* shW = sh + 256 * 64;       // [256][40]
    int tid = threadIdx.x;
    int row0 = blockIdx.x * 64;

    for (int i = tid; i < 64 * 256; i += 320) {
        int r = i & 63, k = i >> 6;
        int gr = row0 + r;
        shH[k * 64 + r] = (gr < N_NODES) ? g_h1[gr * 256 + k] : 0.f;
    }
    for (int i = tid; i < 256 * 40; i += 320) shW[i] = W2[i];
    __syncthreads();

    int tx = tid % 40, ty = tid / 40;   // ty: 0..7 -> rows ty*8..ty*8+7
    int r0 = ty * 8;
    ull acc[4];
    #pragma unroll
    for (int i = 0; i < 4; i++) acc[i] = 0ull;

    #pragma unroll 4
    for (int k = 0; k < 256; k++) {
        float w = shW[k * 40 + tx];
        ull ww = pack2(w, w);
        longlong2 ha = *(const longlong2*)&shH[k * 64 + r0];      // rows r0..r0+3
        longlong2 hb = *(const longlong2*)&shH[k * 64 + r0 + 4];  // rows r0+4..r0+7
        acc[0] = ffma2((ull)ha.x, ww, acc[0]);
        acc[1] = ffma2((ull)ha.y, ww, acc[1]);
        acc[2] = ffma2((ull)hb.x, ww, acc[2]);
        acc[3] = ffma2((ull)hb.y, ww, acc[3]);
    }

    float c[8];
    unpack2(acc[0], c[0], c[1]);
    unpack2(acc[1], c[2], c[3]);
    unpack2(acc[2], c[4], c[5]);
    unpack2(acc[3], c[6], c[7]);
    #pragma unroll
    for (int i = 0; i < 8; i++) {
        int gr = row0 + r0 + i;
        if (gr < N_NODES) g_z2[gr * 40 + tx] = c[i];
    }
}

// ---------------- el2/er2 ----------------
__global__ void elr2_kernel(const float* __restrict__ al2, const float* __restrict__ ar2) {
    int n = blockIdx.x * 256 + threadIdx.x;
    if (n >= N_NODES) return;
    const float4* z4 = (const float4*)&g_z2[n * 40];
    float el = 0.f, er = 0.f;
    #pragma unroll
    for (int i = 0; i < 10; i++) {
        float4 z = z4[i];
        const float4 a = ((const float4*)al2)[i];
        const float4 r = ((const float4*)ar2)[i];
        el += z.x * a.x + z.y * a.y + z.z * a.z + z.w * a.w;
        er += z.x * r.x + z.y * r.y + z.z * r.z + z.w * r.w;
    }
    g_el2[n] = el;
    g_er2[n] = er;
}

// ---------------- edge weights layer 2 ----------------
__global__ void exk2_kernel() {
    int p = blockIdx.x * 256 + threadIdx.x;
    if (p >= N_EDGES) return;
    int s = g_col[p], d = g_dstslot[p];
    float e = g_el2[s] + g_er2[d];
    g_ex2[p] = __expf(lrelu(e));
}

// ---------------- layer-2 aggregation -> out ----------------
// 8 nodes per 320-thread block; 40 threads per node, fully independent threads.
#define AGG2_NPB 8
__global__ void agg2_kernel(const float* __restrict__ b2, float* __restrict__ out) {
    int local = threadIdx.x / 40;           // node slot within block (0..7)
    int j = threadIdx.x - local * 40;       // output column
    int n = blockIdx.x * AGG2_NPB + local;
    if (n >= N_NODES) return;
    int rs = g_rowptr[n], re = g_rowptr[n + 1];
    float acc = 0.f, sumex = 0.f;
    int i = rs;
    for (; i + 4 <= re; i += 4) {
        int s0 = g_col[i], s1 = g_col[i + 1], s2 = g_col[i + 2], s3 = g_col[i + 3];
        float x0 = g_ex2[i + 0];
        float x1 = g_ex2[i + 1];
        float x2 = g_ex2[i + 2];
        float x3 = g_ex2[i + 3];
        float z0 = g_z2[s0 * 40 + j];
        float z1v = g_z2[s1 * 40 + j];
        float z2v = g_z2[s2 * 40 + j];
        float z3v = g_z2[s3 * 40 + j];
        sumex += (x0 + x1) + (x2 + x3);
        acc += x0 * z0;
        acc += x1 * z1v;
        acc += x2 * z2v;
        acc += x3 * z3v;
    }
    for (; i < re; i++) {
        int s = g_col[i];
        float x = g_ex2[i];
        sumex += x;
        acc += x * g_z2[s * 40 + j];
    }
    float v = (sumex > 0.f) ? (acc / sumex) : 0.f;
    out[n * 40 + j] = v + b2[j];
}

// ---------------- launch ----------------
extern "C" void kernel_launch(void* const* d_in, const int* in_sizes, int n_in,
                              void* d_out, int out_size) {
    const float* feat = (const float*)d_in[0];
    const int*   src  = (const int*)d_in[1];
    const int*   dst  = (const int*)d_in[2];
    const float* W1   = (const float*)d_in[3];
    const float* al1  = (const float*)d_in[4];
    const float* ar1  = (const float*)d_in[5];
    const float* b1   = (const float*)d_in[6];
    const float* W2   = (const float*)d_in[7];
    const float* al2  = (const float*)d_in[8];
    const float* ar2  = (const float*)d_in[9];
    const float* b2   = (const float*)d_in[10];
    float* out = (float*)d_out;
    (void)in_sizes; (void)n_in; (void)out_size;

    zero_deg_kernel<<<NB_SCAN, 1024>>>();
    count_kernel<<<(N_EDGES + 255) / 256, 256>>>(dst);
    scan1_kernel<<<NB_SCAN, 1024>>>();

    // gemm1 placed in the ncu-captured launch slot (independent of CSR chain)
    const int smem1 = (128 * 256 + 128 * 64 + 512) * sizeof(float);   // 165888
    cudaFuncSetAttribute(gemm1_kernel, cudaFuncAttributeMaxDynamicSharedMemorySize, smem1);
    gemm1_kernel<<<(N_NODES + 63) / 64, 512, smem1>>>(feat, W1, al1, ar1);

    scan2_kernel<<<1, 32>>>();
    scan3_kernel<<<NB_SCAN, 1024>>>();
    scatter_kernel<<<(N_EDGES + 255) / 256, 256>>>(src, dst);

    exk1_kernel<<<(N_EDGES * H1 + 255) / 256, 256>>>();
    agg1_kernel<<<N_NODES, 256>>>(b1);

    const int smem2 = (256 * 64 + 256 * 40) * sizeof(float);    // 106496
    cudaFuncSetAttribute(gemm2_kernel, cudaFuncAttributeMaxDynamicSharedMemorySize, smem2);
    gemm2_kernel<<<(N_NODES + 63) / 64, 320, smem2>>>(W2);

    elr2_kernel<<<(N_NODES + 255) / 256, 256>>>(al2, ar2);
    exk2_kernel<<<(N_EDGES + 255) / 256, 256>>>();
    agg2_kernel<<<(N_NODES + AGG2_NPB - 1) / AGG2_NPB, AGG2_NPB * 40>>>(b2, out);
}